// round 1
// baseline (speedup 1.0000x reference)
#include <cuda_runtime.h>
#include <math.h>

#define NN 200000
#define NE 3200000
#define NP 4096
#define SCAN_T 1024
#define SCAN_NB 196   // ceil(NN/1024)

// ---------------- scratch (__device__ globals; no allocation) ----------------
__device__ int d_deg[NN];
__device__ int d_off[NN + 1];
__device__ int d_cursor[NN];
__device__ int d_bsum[SCAN_NB];
__device__ int d_boff[SCAN_NB];
__device__ int d_ssrc[NE];          // src indices sorted (grouped) by dst

// ---------------- build CSR: deg -> scan -> scatter ----------------
__global__ void k_zero_deg() {
    int i = blockIdx.x * blockDim.x + threadIdx.x;
    if (i < NN) d_deg[i] = 0;
}

__global__ void k_hist(const int* __restrict__ dst) {
    int e = blockIdx.x * blockDim.x + threadIdx.x;
    if (e < NE) atomicAdd(&d_deg[dst[e]], 1);
}

__global__ void k_scan1() {
    __shared__ int s[SCAN_T];
    int i = blockIdx.x * SCAN_T + threadIdx.x;
    int v = (i < NN) ? d_deg[i] : 0;
    s[threadIdx.x] = v;
    __syncthreads();
    for (int o = 1; o < SCAN_T; o <<= 1) {
        int t = (threadIdx.x >= o) ? s[threadIdx.x - o] : 0;
        __syncthreads();
        s[threadIdx.x] += t;
        __syncthreads();
    }
    if (i < NN) d_off[i] = s[threadIdx.x];           // inclusive scan
    if (threadIdx.x == SCAN_T - 1) d_bsum[blockIdx.x] = s[SCAN_T - 1];
}

__global__ void k_scan2() {
    if (threadIdx.x == 0 && blockIdx.x == 0) {
        int run = 0;
        for (int b = 0; b < SCAN_NB; b++) { d_boff[b] = run; run += d_bsum[b]; }
    }
}

__global__ void k_scan3() {
    int i = blockIdx.x * SCAN_T + threadIdx.x;
    if (i < NN) {
        int excl = d_off[i] - d_deg[i] + d_boff[blockIdx.x];
        d_off[i] = excl;
        d_cursor[i] = excl;
    }
    if (i == 0) d_off[NN] = NE;
}

__global__ void k_scatter(const int* __restrict__ src, const int* __restrict__ dst) {
    int e = blockIdx.x * blockDim.x + threadIdx.x;
    if (e < NE) {
        int p = atomicAdd(&d_cursor[dst[e]], 1);
        d_ssrc[p] = src[e];
    }
}

// ---------------- fused SAGE layer: mean-agg + self/neigh matmul + tanh ----------------
// One warp per node. lane = feature index (32 feats).
__global__ void k_sage_layer(const float* __restrict__ hprev, int hstride,
                             float* __restrict__ concat, int layer,
                             const float* __restrict__ Ws, const float* __restrict__ Wn,
                             const float* __restrict__ b) {
    __shared__ float sWs[1024], sWn[1024], sb[32];
    int tid = threadIdx.x;
    for (int i = tid; i < 1024; i += blockDim.x) { sWs[i] = Ws[i]; sWn[i] = Wn[i]; }
    if (tid < 32) sb[tid] = b[tid];
    __syncthreads();

    int warp = tid >> 5, lane = tid & 31;
    int n = blockIdx.x * (blockDim.x >> 5) + warp;
    if (n >= NN) return;

    float x = hprev[(size_t)n * hstride + lane];

    int e0 = d_off[n], e1 = d_off[n + 1];
    float acc = 0.f;
    for (int base = e0; base < e1; base += 32) {
        int ee = base + lane;
        int idx = (ee < e1) ? d_ssrc[ee] : -1;
        int cnt = e1 - base;
        if (cnt >= 32) {
            #pragma unroll
            for (int j = 0; j < 32; j++) {
                int s = __shfl_sync(0xffffffffu, idx, j);
                acc += hprev[(size_t)s * hstride + lane];
            }
        } else {
            for (int j = 0; j < cnt; j++) {
                int s = __shfl_sync(0xffffffffu, idx, j);
                acc += hprev[(size_t)s * hstride + lane];
            }
        }
    }
    float degf = (float)(e1 - e0);
    float mean = acc / fmaxf(degf, 1.0f);

    float r = sb[lane];
    #pragma unroll
    for (int k = 0; k < 32; k++) {
        float xk = __shfl_sync(0xffffffffu, x, k);
        float mk = __shfl_sync(0xffffffffu, mean, k);
        r += xk * sWs[k * 32 + lane] + mk * sWn[k * 32 + lane];
    }
    concat[(size_t)n * 128 + layer * 32 + lane] = tanhf(r);
}

// ---------------- pair MLP: relu(pair @ W1 + b1) @ W2 + b2 -> sigmoid ----------------
// 128 threads/block (one per hidden unit). W1 (128KB) stays L1-resident per block.
__global__ void k_mlp(const float* __restrict__ concat,
                      const int* __restrict__ uidx, const int* __restrict__ iidx,
                      const float* __restrict__ W1, const float* __restrict__ bl1,
                      const float* __restrict__ W2, const float* __restrict__ bl2,
                      float* __restrict__ score, int pairs_per_block) {
    __shared__ float spair[256];
    __shared__ float sred[4];
    int tid = threadIdx.x;   // 0..127
    float w2 = W2[tid];
    float b1 = bl1[tid];
    float b2 = bl2[0];
    int p0 = blockIdx.x * pairs_per_block;
    int p1 = min(NP, p0 + pairs_per_block);
    for (int p = p0; p < p1; p++) {
        int u = uidx[p], it = iidx[p];
        spair[tid]       = concat[(size_t)u  * 128 + tid];
        spair[128 + tid] = concat[(size_t)it * 128 + tid];
        __syncthreads();
        float acc = b1;
        #pragma unroll 8
        for (int k = 0; k < 256; k++) acc += spair[k] * W1[k * 128 + tid];
        float h = fmaxf(acc, 0.f) * w2;
        #pragma unroll
        for (int o = 16; o > 0; o >>= 1) h += __shfl_down_sync(0xffffffffu, h, o);
        if ((tid & 31) == 0) sred[tid >> 5] = h;
        __syncthreads();
        if (tid == 0) {
            float s = sred[0] + sred[1] + sred[2] + sred[3] + b2;
            score[p] = 1.0f / (1.0f + expf(-s));
        }
        __syncthreads();
    }
}

// ---------------- launch ----------------
extern "C" void kernel_launch(void* const* d_in, const int* in_sizes, int n_in,
                              void* d_out, int out_size) {
    const float* x    = (const float*)d_in[0];
    const int*   src  = (const int*)d_in[1];
    const int*   dst  = (const int*)d_in[2];
    const int*   uidx = (const int*)d_in[3];
    const int*   iidx = (const int*)d_in[4];
    const float* Ws[4] = { (const float*)d_in[5], (const float*)d_in[8],
                           (const float*)d_in[11], (const float*)d_in[14] };
    const float* Wn[4] = { (const float*)d_in[6], (const float*)d_in[9],
                           (const float*)d_in[12], (const float*)d_in[15] };
    const float* bb[4] = { (const float*)d_in[7], (const float*)d_in[10],
                           (const float*)d_in[13], (const float*)d_in[16] };
    const float* W1  = (const float*)d_in[17];
    const float* bl1 = (const float*)d_in[18];
    const float* W2  = (const float*)d_in[19];
    const float* bl2 = (const float*)d_in[20];

    float* out    = (float*)d_out;
    float* score  = out;              // first output of the tuple: [4096]
    float* concat = out + NP;         // second output: [200000, 128]

    // Build CSR (counting sort of edges by dst) — done once per call, reused by all 4 layers.
    k_zero_deg<<<(NN + 255) / 256, 256>>>();
    k_hist<<<(NE + 255) / 256, 256>>>(dst);
    k_scan1<<<SCAN_NB, SCAN_T>>>();
    k_scan2<<<1, 32>>>();
    k_scan3<<<SCAN_NB, SCAN_T>>>();
    k_scatter<<<(NE + 255) / 256, 256>>>(src, dst);

    // 4 fused SAGE layers; each writes its 32-col slice of the concat output directly.
    const int TPB = 256;                       // 8 warps = 8 nodes per block
    const int NBLK = (NN + 7) / 8;
    k_sage_layer<<<NBLK, TPB>>>(x, 32, concat, 0, Ws[0], Wn[0], bb[0]);
    for (int L = 1; L < 4; L++) {
        k_sage_layer<<<NBLK, TPB>>>(concat + (L - 1) * 32, 128, concat, L,
                                    Ws[L], Wn[L], bb[L]);
    }

    // Pair-scoring MLP.
    const int MLP_BLOCKS = 128;
    k_mlp<<<MLP_BLOCKS, 128>>>(concat, uidx, iidx, W1, bl1, W2, bl2, score,
                               NP / MLP_BLOCKS);
}

// round 2
// speedup vs baseline: 1.0011x; 1.0011x over previous
#include <cuda_runtime.h>
#include <math.h>

#define NN 200000
#define NE 3200000
#define NP 4096
#define SCAN_T 1024
#define SCAN_NB 196   // ceil(NN/1024)

// ---------------- scratch (__device__ globals; no allocation) ----------------
__device__ int d_deg[NN];
__device__ int d_off[NN + 1];
__device__ int d_cursor[NN];
__device__ int d_bsum[SCAN_NB];
__device__ int d_boff[SCAN_NB];
__device__ int d_ssrc[NE];          // src indices sorted (grouped) by dst

// ---------------- build CSR: deg -> scan -> scatter ----------------
__global__ void k_zero_deg() {
    int i = blockIdx.x * blockDim.x + threadIdx.x;
    if (i < NN) d_deg[i] = 0;
}

__global__ void k_hist(const int* __restrict__ dst) {
    int e = blockIdx.x * blockDim.x + threadIdx.x;
    if (e < NE) atomicAdd(&d_deg[dst[e]], 1);
}

__global__ void k_scan1() {
    __shared__ int s[SCAN_T];
    int i = blockIdx.x * SCAN_T + threadIdx.x;
    int v = (i < NN) ? d_deg[i] : 0;
    s[threadIdx.x] = v;
    __syncthreads();
    for (int o = 1; o < SCAN_T; o <<= 1) {
        int t = (threadIdx.x >= o) ? s[threadIdx.x - o] : 0;
        __syncthreads();
        s[threadIdx.x] += t;
        __syncthreads();
    }
    if (i < NN) d_off[i] = s[threadIdx.x];           // inclusive scan
    if (threadIdx.x == SCAN_T - 1) d_bsum[blockIdx.x] = s[SCAN_T - 1];
}

// parallel scan of the 196 block sums (single block, 256 threads)
__global__ void k_scan2() {
    __shared__ int s[256];
    int tid = threadIdx.x;
    int v = (tid < SCAN_NB) ? d_bsum[tid] : 0;
    s[tid] = v;
    __syncthreads();
    for (int o = 1; o < 256; o <<= 1) {
        int t = (tid >= o) ? s[tid - o] : 0;
        __syncthreads();
        s[tid] += t;
        __syncthreads();
    }
    if (tid < SCAN_NB) d_boff[tid] = s[tid] - v;     // exclusive
}

__global__ void k_scan3() {
    int i = blockIdx.x * SCAN_T + threadIdx.x;
    if (i < NN) {
        int excl = d_off[i] - d_deg[i] + d_boff[blockIdx.x];
        d_off[i] = excl;
        d_cursor[i] = excl;
    }
    if (i == 0) d_off[NN] = NE;
}

__global__ void k_scatter(const int* __restrict__ src, const int* __restrict__ dst) {
    int e = blockIdx.x * blockDim.x + threadIdx.x;
    if (e < NE) {
        int p = atomicAdd(&d_cursor[dst[e]], 1);
        d_ssrc[p] = src[e];
    }
}

// ---------------- fused SAGE layer: mean-agg + self/neigh matmul + tanh ----------------
// One warp per node. Gather phase: lane = (edge-group l>>3, float4-chunk l&7);
// 4 edges per warp-iteration via LDG.128. Matmul phase: lane = feature index.
__global__ void k_sage_layer(const float* __restrict__ hprev, int strideFloats,
                             float* __restrict__ concat, int layer,
                             const float* __restrict__ Ws, const float* __restrict__ Wn,
                             const float* __restrict__ b) {
    __shared__ float sWs[1024], sWn[1024], sb[32];
    __shared__ float4 sxch[8][8];   // [warp][chunk] transpose buffer
    int tid = threadIdx.x;
    for (int i = tid; i < 1024; i += blockDim.x) { sWs[i] = Ws[i]; sWn[i] = Wn[i]; }
    if (tid < 32) sb[tid] = b[tid];
    __syncthreads();

    int warp = tid >> 5, lane = tid & 31;
    int n = blockIdx.x * (blockDim.x >> 5) + warp;
    if (n >= NN) return;

    int grp = lane >> 3;      // edge group 0..3
    int chk = lane & 7;       // float4 chunk 0..7 (features 4*chk .. 4*chk+3)

    const char* hbase = (const char*)hprev;
    int rowBytes = strideFloats * 4;
    int chunkOff = chk * 16;

    float x = hprev[n * strideFloats + lane];   // self features (lane = feature)

    int e0 = d_off[n], e1 = d_off[n + 1];
    float4 acc = make_float4(0.f, 0.f, 0.f, 0.f);

    for (int base = e0; base < e1; base += 32) {
        int cnt = e1 - base;                    // edges in this 32-chunk (1..32)
        int ee = base + lane;
        int idx = (ee < e1) ? d_ssrc[ee] : 0;   // pad with node 0 (safe addr)
        if (cnt >= 32) {
            #pragma unroll
            for (int it = 0; it < 8; it++) {
                int s = __shfl_sync(0xffffffffu, idx, it * 4 + grp);
                float4 p = *(const float4*)(hbase + s * rowBytes + chunkOff);
                acc.x += p.x; acc.y += p.y; acc.z += p.z; acc.w += p.w;
            }
        } else {
            int nIt = (cnt + 3) >> 2;
            for (int it = 0; it < nIt; it++) {
                int g = it * 4 + grp;
                int s = __shfl_sync(0xffffffffu, idx, g & 31);
                float4 p = *(const float4*)(hbase + s * rowBytes + chunkOff);
                if (g < cnt) {
                    acc.x += p.x; acc.y += p.y; acc.z += p.z; acc.w += p.w;
                }
            }
        }
    }
    // reduce the 4 edge-groups: lanes {chk, chk+8, chk+16, chk+24} hold partials
    acc.x += __shfl_xor_sync(0xffffffffu, acc.x, 8);
    acc.y += __shfl_xor_sync(0xffffffffu, acc.y, 8);
    acc.z += __shfl_xor_sync(0xffffffffu, acc.z, 8);
    acc.w += __shfl_xor_sync(0xffffffffu, acc.w, 8);
    acc.x += __shfl_xor_sync(0xffffffffu, acc.x, 16);
    acc.y += __shfl_xor_sync(0xffffffffu, acc.y, 16);
    acc.z += __shfl_xor_sync(0xffffffffu, acc.z, 16);
    acc.w += __shfl_xor_sync(0xffffffffu, acc.w, 16);

    float degf = (float)(e1 - e0);
    float inv = 1.0f / fmaxf(degf, 1.0f);

    // transpose: chunk layout -> per-lane feature
    if (lane < 8) sxch[warp][lane] = acc;
    __syncwarp();
    float mean = ((const float*)&sxch[warp][lane >> 2])[lane & 3] * inv;

    float r = sb[lane];
    #pragma unroll
    for (int k = 0; k < 32; k++) {
        float xk = __shfl_sync(0xffffffffu, x, k);
        float mk = __shfl_sync(0xffffffffu, mean, k);
        r += xk * sWs[k * 32 + lane] + mk * sWn[k * 32 + lane];
    }
    concat[n * 128 + layer * 32 + lane] = tanhf(r);
}

// ---------------- pair MLP: relu(pair @ W1 + b1) @ W2 + b2 -> sigmoid ----------------
__global__ void k_mlp(const float* __restrict__ concat,
                      const int* __restrict__ uidx, const int* __restrict__ iidx,
                      const float* __restrict__ W1, const float* __restrict__ bl1,
                      const float* __restrict__ W2, const float* __restrict__ bl2,
                      float* __restrict__ score, int pairs_per_block) {
    __shared__ float spair[256];
    __shared__ float sred[4];
    int tid = threadIdx.x;   // 0..127
    float w2 = W2[tid];
    float b1 = bl1[tid];
    float b2 = bl2[0];
    int p0 = blockIdx.x * pairs_per_block;
    int p1 = min(NP, p0 + pairs_per_block);
    for (int p = p0; p < p1; p++) {
        int u = uidx[p], it = iidx[p];
        spair[tid]       = concat[u  * 128 + tid];
        spair[128 + tid] = concat[it * 128 + tid];
        __syncthreads();
        float acc = b1;
        #pragma unroll 8
        for (int k = 0; k < 256; k++) acc += spair[k] * W1[k * 128 + tid];
        float h = fmaxf(acc, 0.f) * w2;
        #pragma unroll
        for (int o = 16; o > 0; o >>= 1) h += __shfl_down_sync(0xffffffffu, h, o);
        if ((tid & 31) == 0) sred[tid >> 5] = h;
        __syncthreads();
        if (tid == 0) {
            float s = sred[0] + sred[1] + sred[2] + sred[3] + b2;
            score[p] = 1.0f / (1.0f + expf(-s));
        }
        __syncthreads();
    }
}

// ---------------- launch ----------------
extern "C" void kernel_launch(void* const* d_in, const int* in_sizes, int n_in,
                              void* d_out, int out_size) {
    const float* x    = (const float*)d_in[0];
    const int*   src  = (const int*)d_in[1];
    const int*   dst  = (const int*)d_in[2];
    const int*   uidx = (const int*)d_in[3];
    const int*   iidx = (const int*)d_in[4];
    const float* Ws[4] = { (const float*)d_in[5], (const float*)d_in[8],
                           (const float*)d_in[11], (const float*)d_in[14] };
    const float* Wn[4] = { (const float*)d_in[6], (const float*)d_in[9],
                           (const float*)d_in[12], (const float*)d_in[15] };
    const float* bb[4] = { (const float*)d_in[7], (const float*)d_in[10],
                           (const float*)d_in[13], (const float*)d_in[16] };
    const float* W1  = (const float*)d_in[17];
    const float* bl1 = (const float*)d_in[18];
    const float* W2  = (const float*)d_in[19];
    const float* bl2 = (const float*)d_in[20];

    float* out    = (float*)d_out;
    float* score  = out;              // first output of the tuple: [4096]
    float* concat = out + NP;         // second output: [200000, 128]

    // Build CSR (counting sort of edges by dst) — reused by all 4 layers.
    k_zero_deg<<<(NN + 255) / 256, 256>>>();
    k_hist<<<(NE + 255) / 256, 256>>>(dst);
    k_scan1<<<SCAN_NB, SCAN_T>>>();
    k_scan2<<<1, 256>>>();
    k_scan3<<<SCAN_NB, SCAN_T>>>();
    k_scatter<<<(NE + 255) / 256, 256>>>(src, dst);

    // 4 fused SAGE layers; each writes its 32-col slice of the concat output directly.
    const int TPB = 256;                       // 8 warps = 8 nodes per block
    const int NBLK = (NN + 7) / 8;
    k_sage_layer<<<NBLK, TPB>>>(x, 32, concat, 0, Ws[0], Wn[0], bb[0]);
    for (int L = 1; L < 4; L++) {
        k_sage_layer<<<NBLK, TPB>>>(concat + (L - 1) * 32, 128, concat, L,
                                    Ws[L], Wn[L], bb[L]);
    }

    // Pair-scoring MLP.
    const int MLP_BLOCKS = 128;
    k_mlp<<<MLP_BLOCKS, 128>>>(concat, uidx, iidx, W1, bl1, W2, bl2, score,
                               NP / MLP_BLOCKS);
}